// round 13
// baseline (speedup 1.0000x reference)
#include <cuda_runtime.h>
#include <cstdint>

#define N_QUERIES 262144
#define N_SLOTS   1024
#define KEY_DIM   64
#define VAL_DIM   64
#define TOPK      4
#define LR        0.001f
#define MOMENTUM  0.9f
#define WD        0.0001f

#define RET_ELEMS  (N_QUERIES * TOPK * VAL_DIM)   // 67108864
#define SLOT_ELEMS (N_SLOTS * VAL_DIM)            // 65536
#define CAP 96                                    // candidate buffer per lane
#define BANDI 1500.0f                             // err band, int-dot units (~11 sigma)

typedef unsigned int u32;

__device__ __forceinline__ int dp4a_s(int a, int b, int c) {
    int d;
    asm("dp4a.s32.s32 %0, %1, %2, %3;" : "=r"(d) : "r"(a), "r"(b), "r"(c));
    return d;
}

// ---------------- scratch (device globals; no allocation allowed) -----------
__device__ int   g_idx[N_QUERIES * TOPK];                 // 4 MB
__device__ __align__(16) float g_sg[SLOT_ELEMS];
__device__ float g_cnt[N_SLOTS];
__device__ __align__(16) int4 g_k8[N_SLOTS * 4];          // int8 keys, 64 KB
__device__ float g_ksc[N_SLOTS];                          // per-slot dequant scale

// ---------------- kernel 0: quantize keys + zero accumulators ---------------
__global__ void prep_kernel(const float* __restrict__ keys) {
    int i = blockIdx.x * 256 + threadIdx.x;    // 65536 threads
    if (i < SLOT_ELEMS) g_sg[i] = 0.0f;
    if (i < N_SLOTS) {
        g_cnt[i] = 0.0f;
        const float* kr = keys + (size_t)i * KEY_DIM;
        float mx = 0.0f;
#pragma unroll
        for (int d = 0; d < KEY_DIM; d++) mx = fmaxf(mx, fabsf(kr[d]));
        mx = fmaxf(mx, 1e-30f);
        float sc = 127.0f / mx;
        g_ksc[i] = mx * (1.0f / 127.0f);
#pragma unroll
        for (int c = 0; c < 4; c++) {
            int w[4];
#pragma unroll
            for (int wi = 0; wi < 4; wi++) {
                int d0 = c * 16 + wi * 4;
                int b0 = __float2int_rn(kr[d0 + 0] * sc) & 0xFF;
                int b1 = __float2int_rn(kr[d0 + 1] * sc) & 0xFF;
                int b2 = __float2int_rn(kr[d0 + 2] * sc) & 0xFF;
                int b3 = __float2int_rn(kr[d0 + 3] * sc) & 0xFF;
                w[wi] = b0 | (b1 << 8) | (b2 << 16) | (b3 << 24);
            }
            g_k8[i * 4 + c] = make_int4(w[0], w[1], w[2], w[3]);
        }
    }
}

// ---------------- kernel 1: interval dp4a filter + exact top-4 + gather -----
// 1 query/lane. Keys (int8) read via warp-uniform __ldg (L1-resident 68 KB).
// Branchless scan: 8 FMNMX maintain 4th-largest pessimistic value; optimistic
// value above it => append j to per-lane SMEM buffer (predicated, ~33 avg).
// Containment is deterministic given the error band. Then exact sequential
// fp32 recheck of buffered candidates in ascending-j order (stable ties).
#define SMEM_BUF  0                     // CAP*256*4 = 98304 B
#define SMEM_FIDX (CAP * 256 * 4)       // 256*4 int = 4096 B
#define SMEM_SZ   (SMEM_FIDX + 4096)

__global__ void __launch_bounds__(256, 2)
simtopk_kernel(const float* __restrict__ queries,
               const float* __restrict__ keys,
               const float* __restrict__ vals,
               float* __restrict__ retrieved) {
    extern __shared__ char smem[];
    int* sbuf = (int*)(smem + SMEM_BUF);    // [entry][tid] stride 256
    int* sfid = (int*)(smem + SMEM_FIDX);

    const int tid  = threadIdx.x;
    const int wid  = tid >> 5, lane = tid & 31;
    const int q    = blockIdx.x * 256 + tid;

    // quantize own query in-register
    const float4* qr = (const float4*)(queries + (size_t)q * KEY_DIM);
    float mx = 0.0f;
#pragma unroll
    for (int c = 0; c < 16; c++) {
        float4 v = __ldg(qr + c);
        mx = fmaxf(mx, fmaxf(fmaxf(fabsf(v.x), fabsf(v.y)),
                             fmaxf(fabsf(v.z), fabsf(v.w))));
    }
    mx = fmaxf(mx, 1e-30f);
    const float qsc  = 127.0f / mx;
    const float qinv = mx * (1.0f / 127.0f);
    int qi[16];
#pragma unroll
    for (int c = 0; c < 16; c++) {
        float4 v = __ldg(qr + c);
        int b0 = __float2int_rn(v.x * qsc) & 0xFF;
        int b1 = __float2int_rn(v.y * qsc) & 0xFF;
        int b2 = __float2int_rn(v.z * qsc) & 0xFF;
        int b3 = __float2int_rn(v.w * qsc) & 0xFF;
        qi[c] = b0 | (b1 << 8) | (b2 << 16) | (b3 << 24);
    }

    // ---- branchless interval scan over all 1024 slots ----------------------
    float t0 = -1e30f, t1 = -1e30f, t2 = -1e30f, t3 = -1e30f;  // top-4 of vp
    int cnt = 0;
#pragma unroll 2
    for (int j = 0; j < N_SLOTS; j++) {
        const int4* kp = &g_k8[j * 4];
        int4 k0 = __ldg(kp + 0);
        int4 k1 = __ldg(kp + 1);
        int4 k2 = __ldg(kp + 2);
        int4 k3 = __ldg(kp + 3);
        float ksc = __ldg(&g_ksc[j]);
        int a0 = 0, a1 = 0, a2 = 0, a3 = 0;
        a0 = dp4a_s(k0.x, qi[0],  a0); a0 = dp4a_s(k0.y, qi[1],  a0);
        a0 = dp4a_s(k0.z, qi[2],  a0); a0 = dp4a_s(k0.w, qi[3],  a0);
        a1 = dp4a_s(k1.x, qi[4],  a1); a1 = dp4a_s(k1.y, qi[5],  a1);
        a1 = dp4a_s(k1.z, qi[6],  a1); a1 = dp4a_s(k1.w, qi[7],  a1);
        a2 = dp4a_s(k2.x, qi[8],  a2); a2 = dp4a_s(k2.y, qi[9],  a2);
        a2 = dp4a_s(k2.z, qi[10], a2); a2 = dp4a_s(k2.w, qi[11], a2);
        a3 = dp4a_s(k3.x, qi[12], a3); a3 = dp4a_s(k3.y, qi[13], a3);
        a3 = dp4a_s(k3.z, qi[14], a3); a3 = dp4a_s(k3.w, qi[15], a3);
        float df = (float)((a0 + a1) + (a2 + a3));
        float t  = qinv * ksc;
        float vb = (df + BANDI) * t;               // optimistic
        float vp = fmaf(-2.0f * BANDI, t, vb);     // pessimistic

        // append candidate (predicated; threshold BEFORE update => superset)
        if (vb > t3 && cnt < CAP) { sbuf[cnt * 256 + tid] = j; cnt++; }

        // branchless sorted insert of vp into (t0>=t1>=t2>=t3)
        float r = vp, m;
        m = fmaxf(t0, r); r = fminf(t0, r); t0 = m;
        m = fmaxf(t1, r); r = fminf(t1, r); t1 = m;
        m = fmaxf(t2, r); r = fminf(t2, r); t2 = m;
        t3 = fmaxf(t3, r);
    }

    // ---- exact recheck of buffered candidates (ascending j order) ----------
    float bv[4] = {-1e30f, -1e30f, -1e30f, -1e30f};
    int   bi[4] = {0, 0, 0, 0};
    for (int e = 0; e < CAP; e++) {
        if (__all_sync(0xFFFFFFFFu, e >= cnt)) break;
        bool act = (e < cnt);
        int  j   = sbuf[(act ? e : 0) * 256 + tid];
        const float4* kr = (const float4*)(keys + (size_t)j * KEY_DIM);
        float acc = 0.0f;
#pragma unroll
        for (int ch = 0; ch < 16; ch++) {
            float4 qc = __ldg(qr + ch);
            float4 kk = __ldg(kr + ch);
            acc = fmaf(qc.x, kk.x, acc);
            acc = fmaf(qc.y, kk.y, acc);
            acc = fmaf(qc.z, kk.z, acc);
            acc = fmaf(qc.w, kk.w, acc);
        }
        if (act && acc > bv[3]) {                  // strict >: stable ties
            if (acc > bv[0]) {
                bv[3]=bv[2]; bi[3]=bi[2]; bv[2]=bv[1]; bi[2]=bi[1];
                bv[1]=bv[0]; bi[1]=bi[0]; bv[0]=acc;  bi[0]=j;
            } else if (acc > bv[1]) {
                bv[3]=bv[2]; bi[3]=bi[2]; bv[2]=bv[1]; bi[2]=bi[1];
                bv[1]=acc;   bi[1]=j;
            } else if (acc > bv[2]) {
                bv[3]=bv[2]; bi[3]=bi[2]; bv[2]=acc;  bi[2]=j;
            } else { bv[3]=acc; bi[3]=j; }
        }
    }

#pragma unroll
    for (int r = 0; r < 4; r++) {
        g_idx[q * TOPK + r] = bi[r];
        sfid[tid * 4 + r]   = bi[r];
    }
    __syncwarp();

    // ---- cooperative coalesced gather of retrieved rows --------------------
    const int qw = wid * 32;
    for (int qq = 0; qq < 32; qq++) {
        const int qloc = qw + qq;
        float4* out4 =
            (float4*)(retrieved + (size_t)(blockIdx.x * 256 + qloc) * (TOPK * VAL_DIM));
#pragma unroll
        for (int half = 0; half < 2; half++) {
            int jj = lane + half * 32;          // 0..63
            int r  = jj >> 4;
            int e  = jj & 15;
            int id = sfid[qloc * 4 + r];
            out4[jj] = __ldg((const float4*)(vals + (size_t)id * VAL_DIM) + e);
        }
    }
}

// ---------------- kernel 2: scatter grads via direct global v4 reductions ---
#define W_TOTAL (RET_ELEMS / 4)
#define SCAT_THREADS (2048 * 256)
__global__ void __launch_bounds__(256)
scatter_kernel(const float4* __restrict__ grads4) {
    int t = blockIdx.x * 256 + threadIdx.x;
#pragma unroll 4
    for (int it = 0; it < W_TOTAL / SCAT_THREADS; it++) {
        int w    = t + it * SCAT_THREADS;
        int e    = w >> 4;
        int c4   = w & 15;
        int slot = __ldg(&g_idx[e]);
        float4 gg = __ldg(&grads4[w]);
        float* dst = &g_sg[slot * VAL_DIM + c4 * 4];
        asm volatile("red.global.add.v4.f32 [%0], {%1, %2, %3, %4};"
                     :: "l"(dst), "f"(gg.x), "f"(gg.y), "f"(gg.z), "f"(gg.w)
                     : "memory");
        if (c4 == 0) atomicAdd(&g_cnt[slot], 1.0f);
    }
}

// ---------------- kernel 3: finalize vals_new / mom_new ---------------------
__global__ void finalize_kernel(const float* __restrict__ vals,
                                const float* __restrict__ mom,
                                float* __restrict__ out) {
    int i = blockIdx.x * blockDim.x + threadIdx.x;
    if (i >= SLOT_ELEMS) return;
    int   slot = i >> 6;
    float c    = g_cnt[slot];
    float sgv  = g_sg[i];
    bool  nz   = c > 0.0f;
    float avg  = nz ? (sgv / c) : sgv;
    float mn   = MOMENTUM * mom[i] + avg;
    float delta = -LR * (mn + WD * vals[i]);
    float vn   = vals[i] + (nz ? delta : 0.0f);
    out[RET_ELEMS + i]              = vn;
    out[RET_ELEMS + SLOT_ELEMS + i] = mn;
}

// ---------------- launch ----------------------------------------------------
extern "C" void kernel_launch(void* const* d_in, const int* in_sizes, int n_in,
                              void* d_out, int out_size) {
    const float* queries = (const float*)d_in[0];
    const float* keys    = (const float*)d_in[1];
    const float* vals    = (const float*)d_in[2];
    const float* mom     = (const float*)d_in[3];
    const float* grads   = (const float*)d_in[4];
    float* out = (float*)d_out;

    static bool attr_set = false;
    if (!attr_set) {
        cudaFuncSetAttribute(simtopk_kernel,
                             cudaFuncAttributeMaxDynamicSharedMemorySize,
                             SMEM_SZ);
        attr_set = true;
    }

    prep_kernel<<<256, 256>>>(keys);
    simtopk_kernel<<<N_QUERIES / 256, 256, SMEM_SZ>>>(queries, keys, vals, out);
    scatter_kernel<<<2048, 256>>>((const float4*)grads);
    finalize_kernel<<<256, 256>>>(vals, mom, out);
}